// round 3
// baseline (speedup 1.0000x reference)
#include <cuda_runtime.h>
#include <math.h>

// Problem constants
#define BATCH 512
#define F 64
#define H 256
#define H3 768
#define SEQ 256
#define TIN 128
#define TOUT 128

// Recurrence kernel config: 128 CTAs x 4 batches, 256 threads (1 thread = 1 hidden unit)
#define NC 128
#define BC 4
#define NT 256

// ---------------- device scratch (no allocs allowed) ----------------
// Precomputed encoder input projection: gi_enc[t][b][3H] (includes enc_bih)
__device__ float g_gi[(size_t)TIN * BATCH * H3];
// Packed weights: layout dst[(k/4)*O + o] as float4 over 4 consecutive k
__device__ __align__(16) float g_We [H * H3];   // enc_Whh packed  (O=768,K=256)
__device__ __align__(16) float g_Wd [H * H3];   // dec_Whh packed  (O=768,K=256)
__device__ __align__(16) float g_Wie[F * H3];   // enc_Wih packed  (O=768,K=64)
__device__ __align__(16) float g_Wid[F * H3];   // dec_Wih packed  (O=768,K=64)
__device__ __align__(16) float g_rp [H * F];    // reg_W  packed   (O=64, K=256)

// -------- pack: src[O][K] row-major -> dst[(k/4)*O + o] = {src[o][4k4+0..3]} --------
__global__ void pack_w(const float* __restrict__ src, float4* __restrict__ dst, int O, int K) {
    int j = blockIdx.x * blockDim.x + threadIdx.x;
    int n = O * (K >> 2);
    if (j >= n) return;
    int k4 = j / O;
    int o  = j - k4 * O;
    const float* s = src + o * K + (k4 << 2);
    dst[j] = make_float4(s[0], s[1], s[2], s[3]);
}

// -------- encoder input projection: gi[t][b][:] = x[b][t][:] @ Wih.T + bih --------
#define BT 16
__global__ void __launch_bounds__(NT) gi_kernel(const float* __restrict__ x,
                                                const float* __restrict__ bih) {
    __shared__ __align__(16) float sx[BT][F];
    const int t  = threadIdx.x;           // output unit 0..255 (handles o = t, t+256, t+512)
    const int s  = blockIdx.x;            // time step
    const int bb = blockIdx.y * BT;       // batch base

    for (int i = t; i < BT * F; i += NT) {
        int b = i >> 6, f = i & 63;
        sx[b][f] = x[((size_t)(bb + b) * SEQ + s) * F + f];
    }
    __syncthreads();

    float ar[BT], az[BT], an[BT];
    const float br = bih[t], bz = bih[t + H], bn = bih[t + 2 * H];
#pragma unroll
    for (int b = 0; b < BT; b++) { ar[b] = br; az[b] = bz; an[b] = bn; }

    const float4* __restrict__ W   = (const float4*)g_Wie;
    const float4* __restrict__ sx4 = (const float4*)sx;   // [BT][16]
#pragma unroll 4
    for (int k4 = 0; k4 < (F >> 2); k4++) {
        float4 wr = W[k4 * H3 + t];
        float4 wz = W[k4 * H3 + t + H];
        float4 wn = W[k4 * H3 + t + 2 * H];
#pragma unroll
        for (int b = 0; b < BT; b++) {
            float4 xv = sx4[b * (F >> 2) + k4];
            ar[b] = fmaf(wr.x, xv.x, ar[b]); ar[b] = fmaf(wr.y, xv.y, ar[b]);
            ar[b] = fmaf(wr.z, xv.z, ar[b]); ar[b] = fmaf(wr.w, xv.w, ar[b]);
            az[b] = fmaf(wz.x, xv.x, az[b]); az[b] = fmaf(wz.y, xv.y, az[b]);
            az[b] = fmaf(wz.z, xv.z, az[b]); az[b] = fmaf(wz.w, xv.w, az[b]);
            an[b] = fmaf(wn.x, xv.x, an[b]); an[b] = fmaf(wn.y, xv.y, an[b]);
            an[b] = fmaf(wn.z, xv.z, an[b]); an[b] = fmaf(wn.w, xv.w, an[b]);
        }
    }
    float* __restrict__ g = g_gi + ((size_t)s * BATCH + bb) * H3;
#pragma unroll
    for (int b = 0; b < BT; b++) {
        g[b * H3 + t]         = ar[b];
        g[b * H3 + t + H]     = az[b];
        g[b * H3 + t + 2 * H] = an[b];
    }
}

__device__ __forceinline__ float sigf(float v) { return 1.0f / (1.0f + expf(-v)); }

// -------- persistent per-batch-group GRU recurrence --------
__global__ void __launch_bounds__(NT) rnn_kernel(const float* __restrict__ x,
                                                 const float* __restrict__ ebhh,
                                                 const float* __restrict__ dbih,
                                                 const float* __restrict__ dbhh,
                                                 const float* __restrict__ regb,
                                                 float* __restrict__ out) {
    __shared__ __align__(16) float sh[BC][H];   // hidden state
    __shared__ __align__(16) float si[BC][F];   // decoder input

    const int t  = threadIdx.x;           // hidden unit owned by this thread
    const int b0 = blockIdx.x * BC;       // global batch base

    const float ebr = ebhh[t], ebz = ebhh[t + H], ebn = ebhh[t + 2 * H];

#pragma unroll
    for (int b = 0; b < BC; b++) sh[b][t] = 0.0f;
    __syncthreads();

    const float4* __restrict__ sh4 = (const float4*)sh;   // [BC][64]
    const float4* __restrict__ si4 = (const float4*)si;   // [BC][16]
    const float4* __restrict__ We  = (const float4*)g_We;
    const float4* __restrict__ Wd  = (const float4*)g_Wd;
    const float4* __restrict__ Wi  = (const float4*)g_Wid;

    // ================= encoder =================
    for (int s = 0; s < TIN; s++) {
        float ar[BC], az[BC], an[BC];
#pragma unroll
        for (int b = 0; b < BC; b++) { ar[b] = ebr; az[b] = ebz; an[b] = ebn; }

#pragma unroll 4
        for (int k4 = 0; k4 < (H >> 2); k4++) {
            float4 wr = We[k4 * H3 + t];
            float4 wz = We[k4 * H3 + t + H];
            float4 wn = We[k4 * H3 + t + 2 * H];
#pragma unroll
            for (int b = 0; b < BC; b++) {
                float4 hv = sh4[b * (H >> 2) + k4];
                ar[b] = fmaf(wr.x, hv.x, ar[b]); ar[b] = fmaf(wr.y, hv.y, ar[b]);
                ar[b] = fmaf(wr.z, hv.z, ar[b]); ar[b] = fmaf(wr.w, hv.w, ar[b]);
                az[b] = fmaf(wz.x, hv.x, az[b]); az[b] = fmaf(wz.y, hv.y, az[b]);
                az[b] = fmaf(wz.z, hv.z, az[b]); az[b] = fmaf(wz.w, hv.w, az[b]);
                an[b] = fmaf(wn.x, hv.x, an[b]); an[b] = fmaf(wn.y, hv.y, an[b]);
                an[b] = fmaf(wn.z, hv.z, an[b]); an[b] = fmaf(wn.w, hv.w, an[b]);
            }
        }

        const float* __restrict__ gi = g_gi + ((size_t)s * BATCH + b0) * H3;
        float hnew[BC];
#pragma unroll
        for (int b = 0; b < BC; b++) {
            float r = sigf(gi[b * H3 + t]         + ar[b]);
            float z = sigf(gi[b * H3 + t + H]     + az[b]);
            float n = tanhf(fmaf(r, an[b], gi[b * H3 + t + 2 * H]));
            hnew[b] = n + z * (sh[b][t] - n);
        }
        __syncthreads();
#pragma unroll
        for (int b = 0; b < BC; b++) sh[b][t] = hnew[b];
        __syncthreads();
    }

    // ================= decoder =================
    {   // initial input = last source frame
        int b = t >> 6, f = t & 63;
        si[b][f] = x[((size_t)(b0 + b) * SEQ + (TIN - 1)) * F + f];
    }
    const float dbr  = dbih[t]         + dbhh[t];
    const float dbz  = dbih[t + H]     + dbhh[t + H];
    const float dbin = dbih[t + 2 * H];
    const float dbhn = dbhh[t + 2 * H];

    const int ob = t >> 6, oo = t & 63;       // (batch, out-feature) for regression
    const float rb = regb[oo];
    const float4* __restrict__ rp = (const float4*)g_rp;
    __syncthreads();

    for (int s = 0; s < TOUT; s++) {
        float ar[BC], az[BC], ani[BC], anh[BC];
#pragma unroll
        for (int b = 0; b < BC; b++) { ar[b] = dbr; az[b] = dbz; ani[b] = dbin; anh[b] = dbhn; }

        // input projection: si @ dec_Wih.T   (K = 64)
#pragma unroll 4
        for (int k4 = 0; k4 < (F >> 2); k4++) {
            float4 wr = Wi[k4 * H3 + t];
            float4 wz = Wi[k4 * H3 + t + H];
            float4 wn = Wi[k4 * H3 + t + 2 * H];
#pragma unroll
            for (int b = 0; b < BC; b++) {
                float4 xv = si4[b * (F >> 2) + k4];
                ar[b]  = fmaf(wr.x, xv.x, ar[b]);  ar[b]  = fmaf(wr.y, xv.y, ar[b]);
                ar[b]  = fmaf(wr.z, xv.z, ar[b]);  ar[b]  = fmaf(wr.w, xv.w, ar[b]);
                az[b]  = fmaf(wz.x, xv.x, az[b]);  az[b]  = fmaf(wz.y, xv.y, az[b]);
                az[b]  = fmaf(wz.z, xv.z, az[b]);  az[b]  = fmaf(wz.w, xv.w, az[b]);
                ani[b] = fmaf(wn.x, xv.x, ani[b]); ani[b] = fmaf(wn.y, xv.y, ani[b]);
                ani[b] = fmaf(wn.z, xv.z, ani[b]); ani[b] = fmaf(wn.w, xv.w, ani[b]);
            }
        }

        // hidden projection: sh @ dec_Whh.T  (K = 256)
#pragma unroll 4
        for (int k4 = 0; k4 < (H >> 2); k4++) {
            float4 wr = Wd[k4 * H3 + t];
            float4 wz = Wd[k4 * H3 + t + H];
            float4 wn = Wd[k4 * H3 + t + 2 * H];
#pragma unroll
            for (int b = 0; b < BC; b++) {
                float4 hv = sh4[b * (H >> 2) + k4];
                ar[b]  = fmaf(wr.x, hv.x, ar[b]);  ar[b]  = fmaf(wr.y, hv.y, ar[b]);
                ar[b]  = fmaf(wr.z, hv.z, ar[b]);  ar[b]  = fmaf(wr.w, hv.w, ar[b]);
                az[b]  = fmaf(wz.x, hv.x, az[b]);  az[b]  = fmaf(wz.y, hv.y, az[b]);
                az[b]  = fmaf(wz.z, hv.z, az[b]);  az[b]  = fmaf(wz.w, hv.w, az[b]);
                anh[b] = fmaf(wn.x, hv.x, anh[b]); anh[b] = fmaf(wn.y, hv.y, anh[b]);
                anh[b] = fmaf(wn.z, hv.z, anh[b]); anh[b] = fmaf(wn.w, hv.w, anh[b]);
            }
        }

        float hnew[BC];
#pragma unroll
        for (int b = 0; b < BC; b++) {
            float r = sigf(ar[b]);
            float z = sigf(az[b]);
            float n = tanhf(fmaf(r, anh[b], ani[b]));
            hnew[b] = n + z * (sh[b][t] - n);
        }
        __syncthreads();
#pragma unroll
        for (int b = 0; b < BC; b++) sh[b][t] = hnew[b];
        __syncthreads();

        // regression: out = h_new @ reg_W.T + reg_b; also feeds next step input
        float acc = rb;
#pragma unroll 8
        for (int k4 = 0; k4 < (H >> 2); k4++) {
            float4 hv = sh4[ob * (H >> 2) + k4];
            float4 w  = rp[k4 * F + oo];
            acc = fmaf(hv.x, w.x, acc); acc = fmaf(hv.y, w.y, acc);
            acc = fmaf(hv.z, w.z, acc); acc = fmaf(hv.w, w.w, acc);
        }
        out[((size_t)(b0 + ob) * TOUT + s) * F + oo] = acc;
        si[ob][oo] = acc;
        __syncthreads();
    }
}

// ---------------- launch ----------------
extern "C" void kernel_launch(void* const* d_in, const int* in_sizes, int n_in,
                              void* d_out, int out_size) {
    const float* x       = (const float*)d_in[0];
    const float* enc_Wih = (const float*)d_in[1];
    const float* enc_Whh = (const float*)d_in[2];
    const float* enc_bih = (const float*)d_in[3];
    const float* enc_bhh = (const float*)d_in[4];
    const float* dec_Wih = (const float*)d_in[5];
    const float* dec_Whh = (const float*)d_in[6];
    const float* dec_bih = (const float*)d_in[7];
    const float* dec_bhh = (const float*)d_in[8];
    const float* reg_W   = (const float*)d_in[9];
    const float* reg_b   = (const float*)d_in[10];
    float* out = (float*)d_out;

    void *pWe, *pWd, *pWie, *pWid, *pRp;
    cudaGetSymbolAddress(&pWe,  g_We);
    cudaGetSymbolAddress(&pWd,  g_Wd);
    cudaGetSymbolAddress(&pWie, g_Wie);
    cudaGetSymbolAddress(&pWid, g_Wid);
    cudaGetSymbolAddress(&pRp,  g_rp);

    // 1) pack/transpose all weights
    {
        int n;
        n = H3 * (H >> 2); pack_w<<<(n + 255) / 256, 256>>>(enc_Whh, (float4*)pWe,  H3, H);
        n = H3 * (H >> 2); pack_w<<<(n + 255) / 256, 256>>>(dec_Whh, (float4*)pWd,  H3, H);
        n = H3 * (F >> 2); pack_w<<<(n + 255) / 256, 256>>>(enc_Wih, (float4*)pWie, H3, F);
        n = H3 * (F >> 2); pack_w<<<(n + 255) / 256, 256>>>(dec_Wih, (float4*)pWid, H3, F);
        n = F  * (H >> 2); pack_w<<<(n + 255) / 256, 256>>>(reg_W,   (float4*)pRp,  F,  H);
    }

    // 2) encoder input projections for all 128 steps (parallel GEMM)
    {
        dim3 grid(TIN, BATCH / BT);
        gi_kernel<<<grid, NT>>>(x, enc_bih);
    }

    // 3) sequential recurrence, batch-partitioned across CTAs
    rnn_kernel<<<NC, NT>>>(x, enc_bhh, dec_bih, dec_bhh, reg_b, out);
}